// round 2
// baseline (speedup 1.0000x reference)
#include <cuda_runtime.h>

#define HH 512
#define WW 512
#define OW 506
#define BATCH 32
#define CH 3
#define TX 32
#define TY 64
#define ITY 70   // TY + 6
#define ITX 38   // TX + 6

#define F8 0xFFFFFFFFu
__device__ unsigned g_minBits[BATCH] = {
    F8, F8, F8, F8, F8, F8, F8, F8, F8, F8, F8, F8, F8, F8, F8, F8,
    F8, F8, F8, F8, F8, F8, F8, F8, F8, F8, F8, F8, F8, F8, F8, F8};
__device__ unsigned g_maxBits[BATCH];  // zero-init at load
__device__ double g_acc;               // zero-init at load

// Per-image min/max of img2 (values >= 0, so uint ordering == float ordering).
__global__ void minmax_kernel(const float* __restrict__ img2) {
    int b = blockIdx.x;
    const float4* p = (const float4*)(img2 + (size_t)b * (CH * HH * WW));
    const int n4 = CH * HH * WW / 4;
    unsigned lo = F8, hi = 0u;
    for (int i = blockIdx.y * blockDim.x + threadIdx.x; i < n4;
         i += gridDim.y * blockDim.x) {
        float4 v = p[i];
        unsigned a0 = __float_as_uint(v.x), a1 = __float_as_uint(v.y);
        unsigned a2 = __float_as_uint(v.z), a3 = __float_as_uint(v.w);
        lo = min(lo, min(min(a0, a1), min(a2, a3)));
        hi = max(hi, max(max(a0, a1), max(a2, a3)));
    }
    #pragma unroll
    for (int o = 16; o; o >>= 1) {
        lo = min(lo, __shfl_down_sync(F8, lo, o));
        hi = max(hi, __shfl_down_sync(F8, hi, o));
    }
    __shared__ unsigned slo[8], shi[8];
    int lane = threadIdx.x & 31, w = threadIdx.x >> 5;
    if (lane == 0) { slo[w] = lo; shi[w] = hi; }
    __syncthreads();
    if (threadIdx.x == 0) {
        #pragma unroll
        for (int i = 1; i < 8; i++) { lo = min(lo, slo[i]); hi = max(hi, shi[i]); }
        atomicMin(&g_minBits[b], lo);
        atomicMax(&g_maxBits[b], hi);
    }
}

struct SsimSmem {
    float4 hs4[ITY][33];   // (sum x, sum y, sum xx, sum yy) per (row, col)
    float2 sxy[ITY][39];   // raw (x, y) input tile
    float  hs1[ITY][33];   // sum xy
    float  wsum[8];
};

// One 32x64 output tile per block. Horizontal 7-sums into SMEM (vectorized),
// vertical running 7-sums in registers, SSIM, block reduce, one double atomic.
__global__ __launch_bounds__(256) void ssim_kernel(const float* __restrict__ X,
                                                   const float* __restrict__ Y) {
    extern __shared__ char smem_raw[];
    SsimSmem& S = *reinterpret_cast<SsimSmem*>(smem_raw);

    const int z = blockIdx.z;                 // b*3 + c
    const size_t base = (size_t)z * (HH * WW);
    const int x0 = blockIdx.x * TX;
    const int y0 = blockIdx.y * TY;
    const int tid = threadIdx.x, lane = tid & 31, warp = tid >> 5;

    // ---- stage 1: load 70x38 input tile as interleaved float2 ----
    for (int r = warp; r < ITY; r += 8) {
        const int iy = y0 + r;
        const bool yok = iy < HH;
        const float* px = X + base + (size_t)iy * WW;
        const float* py = Y + base + (size_t)iy * WW;
        int c = lane, ix = x0 + c;
        bool ok = yok && (ix < WW);
        S.sxy[r][c] = ok ? make_float2(px[ix], py[ix]) : make_float2(0.f, 0.f);
        if (lane < ITX - 32) {
            c = lane + 32; ix = x0 + c;
            ok = yok && (ix < WW);
            S.sxy[r][c] = ok ? make_float2(px[ix], py[ix]) : make_float2(0.f, 0.f);
        }
    }
    __syncthreads();

    // ---- stage 2: horizontal 7-sums (running), 4 output cols per item ----
    for (int item = tid; item < ITY * 8; item += 256) {
        const int r = item >> 3;
        const int c0 = (item & 7) * 4;
        float s1 = 0.f, s2 = 0.f, s3 = 0.f, s4 = 0.f, s5 = 0.f;
        #pragma unroll
        for (int k = 0; k < 7; k++) {
            float2 v = S.sxy[r][c0 + k];
            s1 += v.x; s2 += v.y;
            s3 += v.x * v.x; s4 += v.y * v.y; s5 += v.x * v.y;
        }
        S.hs4[r][c0] = make_float4(s1, s2, s3, s4);
        S.hs1[r][c0] = s5;
        #pragma unroll
        for (int j = 1; j < 4; j++) {
            float2 vn = S.sxy[r][c0 + 6 + j];
            float2 vo = S.sxy[r][c0 + j - 1];
            s1 += vn.x - vo.x;
            s2 += vn.y - vo.y;
            s3 += vn.x * vn.x - vo.x * vo.x;
            s4 += vn.y * vn.y - vo.y * vo.y;
            s5 += vn.x * vn.y - vo.x * vo.y;
            S.hs4[r][c0 + j] = make_float4(s1, s2, s3, s4);
            S.hs1[r][c0 + j] = s5;
        }
    }
    __syncthreads();

    // per-image constants
    const int b = z / CH;
    const float dr = __uint_as_float(g_maxBits[b]) - __uint_as_float(g_minBits[b]);
    const float C1 = (0.01f * dr) * (0.01f * dr);
    const float C2 = (0.03f * dr) * (0.03f * dr);

    // ---- stage 3: vertical running 7-sums + SSIM; 8 rows per thread ----
    const int c = lane;
    const int r0 = warp * 8;
    float t1 = 0.f, t2 = 0.f, t3 = 0.f, t4 = 0.f, t5 = 0.f;
    #pragma unroll
    for (int k = 0; k < 7; k++) {
        float4 h = S.hs4[r0 + k][c];
        t1 += h.x; t2 += h.y; t3 += h.z; t4 += h.w;
        t5 += S.hs1[r0 + k][c];
    }
    float accS = 0.f;
    const float inv = 1.f / 49.f;
    const float covn = 49.f / 48.f;
    const int ox = x0 + c;
    #pragma unroll
    for (int j = 0; j < 8; j++) {
        if (j > 0) {
            float4 hn = S.hs4[r0 + 6 + j][c];
            float4 ho = S.hs4[r0 + j - 1][c];
            t1 += hn.x - ho.x; t2 += hn.y - ho.y;
            t3 += hn.z - ho.z; t4 += hn.w - ho.w;
            t5 += S.hs1[r0 + 6 + j][c] - S.hs1[r0 + j - 1][c];
        }
        const int oy = y0 + r0 + j;
        if (ox < OW && oy < OW) {
            float ux = t1 * inv, uy = t2 * inv;
            float uxx = t3 * inv, uyy = t4 * inv, uxy = t5 * inv;
            float vx = covn * (uxx - ux * ux);
            float vy = covn * (uyy - uy * uy);
            float vxy = covn * (uxy - ux * uy);
            float A1 = 2.f * ux * uy + C1;
            float A2 = 2.f * vxy + C2;
            float B1 = ux * ux + uy * uy + C1;
            float B2 = vx + vy + C2;
            accS += __fdividef(A1 * A2, B1 * B2);
        }
    }

    // ---- block reduction -> one double atomic ----
    #pragma unroll
    for (int o = 16; o; o >>= 1) accS += __shfl_down_sync(F8, accS, o);
    if (lane == 0) S.wsum[warp] = accS;
    __syncthreads();
    if (tid == 0) {
        float s = 0.f;
        #pragma unroll
        for (int i = 0; i < 8; i++) s += S.wsum[i];
        atomicAdd(&g_acc, (double)s);
    }
}

// Writes the scalar result AND resets accumulators for the next graph replay.
__global__ void finalize_kernel(float* out) {
    int t = threadIdx.x;
    if (t == 0) {
        out[0] = (float)(1.0 - g_acc / ((double)BATCH * CH * OW * OW));
        g_acc = 0.0;
    }
    if (t < BATCH) { g_minBits[t] = F8; g_maxBits[t] = 0u; }
}

extern "C" void kernel_launch(void* const* d_in, const int* in_sizes, int n_in,
                              void* d_out, int out_size) {
    const float* img1 = (const float*)d_in[0];
    const float* img2 = (const float*)d_in[1];

    static_assert(sizeof(SsimSmem) < 228 * 1024, "smem");
    cudaFuncSetAttribute(ssim_kernel, cudaFuncAttributeMaxDynamicSharedMemorySize,
                         (int)sizeof(SsimSmem));

    minmax_kernel<<<dim3(BATCH, 16), 256>>>(img2);
    dim3 grid((OW + TX - 1) / TX, (OW + TY - 1) / TY, BATCH * CH);
    ssim_kernel<<<grid, 256, sizeof(SsimSmem)>>>(img1, img2);
    finalize_kernel<<<1, 64>>>((float*)d_out);
}

// round 3
// speedup vs baseline: 2.3802x; 2.3802x over previous
#include <cuda_runtime.h>

#define HH 512
#define WW 512
#define OW 506
#define BATCH 32
#define CH 3
#define TX 32
#define TY 128
#define ITY 134   // TY + 6

#define F8 0xFFFFFFFFu
__device__ unsigned g_minBits[BATCH] = {
    F8, F8, F8, F8, F8, F8, F8, F8, F8, F8, F8, F8, F8, F8, F8, F8,
    F8, F8, F8, F8, F8, F8, F8, F8, F8, F8, F8, F8, F8, F8, F8, F8};
__device__ unsigned g_maxBits[BATCH];  // zero-init at load
__device__ double g_acc;               // zero-init at load

// Per-image min/max of img2 (values >= 0 -> uint ordering == float ordering).
__global__ void minmax_kernel(const float* __restrict__ img2) {
    int b = blockIdx.x;
    const float4* p = (const float4*)(img2 + (size_t)b * (CH * HH * WW));
    const int n4 = CH * HH * WW / 4;
    unsigned lo = F8, hi = 0u;
    for (int i = blockIdx.y * blockDim.x + threadIdx.x; i < n4;
         i += gridDim.y * blockDim.x) {
        float4 v = p[i];
        unsigned a0 = __float_as_uint(v.x), a1 = __float_as_uint(v.y);
        unsigned a2 = __float_as_uint(v.z), a3 = __float_as_uint(v.w);
        lo = min(lo, min(min(a0, a1), min(a2, a3)));
        hi = max(hi, max(max(a0, a1), max(a2, a3)));
    }
    #pragma unroll
    for (int o = 16; o; o >>= 1) {
        lo = min(lo, __shfl_down_sync(F8, lo, o));
        hi = max(hi, __shfl_down_sync(F8, hi, o));
    }
    __shared__ unsigned slo[8], shi[8];
    int lane = threadIdx.x & 31, w = threadIdx.x >> 5;
    if (lane == 0) { slo[w] = lo; shi[w] = hi; }
    __syncthreads();
    if (threadIdx.x == 0) {
        #pragma unroll
        for (int i = 1; i < 8; i++) { lo = min(lo, slo[i]); hi = max(hi, shi[i]); }
        atomicMin(&g_minBits[b], lo);
        atomicMax(&g_maxBits[b], hi);
    }
}

// Dynamic SMEM: 5 channel planes of horizontal 7-sums, [ITY][33] each.
#define HS(ch, r, c) hs[(ch) * (ITY * 33) + (r) * 33 + (c)]

// One 32x128 output tile per block.
// Stage A: horizontal 7-sums computed from REGISTERS (guarded float4 gmem
//          loads, no raw tile in SMEM), written to SMEM (20 B/output).
// Stage B: vertical running 7-sums over 16 rows/thread + SSIM + reduction.
__global__ __launch_bounds__(256, 2) void ssim_kernel(const float* __restrict__ X,
                                                      const float* __restrict__ Y) {
    extern __shared__ float hs[];
    __shared__ float wsum[8];

    const int z = blockIdx.z;                 // b*3 + c
    const size_t base = (size_t)z * (HH * WW);
    const int x0 = blockIdx.x * TX;
    const int y0 = blockIdx.y * TY;
    const int tid = threadIdx.x, lane = tid & 31, warp = tid >> 5;

    // ---- stage A: horizontal 7-sums, 4 output cols per item ----
    for (int item = tid; item < ITY * 8; item += 256) {
        const int r = item >> 3;
        const int c0 = (item & 7) * 4;
        const int iy = y0 + r;
        const float* px = X + base + (size_t)iy * WW;
        const float* py = Y + base + (size_t)iy * WW;

        float ax[12], ay[12];
        #pragma unroll
        for (int k = 0; k < 3; k++) {
            const int col = x0 + c0 + 4 * k;
            const bool ok = (iy < HH) && (col <= WW - 4);  // col is 16B-aligned
            float4 vx = ok ? *(const float4*)(px + col) : make_float4(0, 0, 0, 0);
            float4 vy = ok ? *(const float4*)(py + col) : make_float4(0, 0, 0, 0);
            ax[4 * k + 0] = vx.x; ax[4 * k + 1] = vx.y;
            ax[4 * k + 2] = vx.z; ax[4 * k + 3] = vx.w;
            ay[4 * k + 0] = vy.x; ay[4 * k + 1] = vy.y;
            ay[4 * k + 2] = vy.z; ay[4 * k + 3] = vy.w;
        }

        float s1 = 0.f, s2 = 0.f, s3 = 0.f, s4 = 0.f, s5 = 0.f;
        #pragma unroll
        for (int k = 0; k < 7; k++) {
            s1 += ax[k]; s2 += ay[k];
            s3 += ax[k] * ax[k]; s4 += ay[k] * ay[k]; s5 += ax[k] * ay[k];
        }
        HS(0, r, c0) = s1; HS(1, r, c0) = s2; HS(2, r, c0) = s3;
        HS(3, r, c0) = s4; HS(4, r, c0) = s5;
        #pragma unroll
        for (int j = 1; j < 4; j++) {
            const float xn = ax[6 + j], yn = ay[6 + j];
            const float xo = ax[j - 1], yo = ay[j - 1];
            s1 += xn - xo;
            s2 += yn - yo;
            s3 += xn * xn - xo * xo;
            s4 += yn * yn - yo * yo;
            s5 += xn * yn - xo * yo;
            HS(0, r, c0 + j) = s1; HS(1, r, c0 + j) = s2; HS(2, r, c0 + j) = s3;
            HS(3, r, c0 + j) = s4; HS(4, r, c0 + j) = s5;
        }
    }
    __syncthreads();

    // per-image constants
    const int b = z / CH;
    const float dr = __uint_as_float(g_maxBits[b]) - __uint_as_float(g_minBits[b]);
    const float C1 = (0.01f * dr) * (0.01f * dr);
    const float C2 = (0.03f * dr) * (0.03f * dr);

    // ---- stage B: vertical running 7-sums + SSIM; 16 rows per thread ----
    const int c = lane;
    const int r0 = warp * 16;
    float t1 = 0.f, t2 = 0.f, t3 = 0.f, t4 = 0.f, t5 = 0.f;
    #pragma unroll
    for (int k = 0; k < 7; k++) {
        t1 += HS(0, r0 + k, c); t2 += HS(1, r0 + k, c); t3 += HS(2, r0 + k, c);
        t4 += HS(3, r0 + k, c); t5 += HS(4, r0 + k, c);
    }
    float accS = 0.f;
    const float inv = 1.f / 49.f;
    const float covn = 49.f / 48.f;
    const int ox = x0 + c;
    #pragma unroll
    for (int j = 0; j < 16; j++) {
        if (j > 0) {
            t1 += HS(0, r0 + 6 + j, c) - HS(0, r0 + j - 1, c);
            t2 += HS(1, r0 + 6 + j, c) - HS(1, r0 + j - 1, c);
            t3 += HS(2, r0 + 6 + j, c) - HS(2, r0 + j - 1, c);
            t4 += HS(3, r0 + 6 + j, c) - HS(3, r0 + j - 1, c);
            t5 += HS(4, r0 + 6 + j, c) - HS(4, r0 + j - 1, c);
        }
        const int oy = y0 + r0 + j;
        if (ox < OW && oy < OW) {
            float ux = t1 * inv, uy = t2 * inv;
            float uxx = t3 * inv, uyy = t4 * inv, uxy = t5 * inv;
            float vx = covn * (uxx - ux * ux);
            float vy = covn * (uyy - uy * uy);
            float vxy = covn * (uxy - ux * uy);
            float A1 = 2.f * ux * uy + C1;
            float A2 = 2.f * vxy + C2;
            float B1 = ux * ux + uy * uy + C1;
            float B2 = vx + vy + C2;
            accS += __fdividef(A1 * A2, B1 * B2);
        }
    }

    // ---- block reduction -> one double atomic ----
    #pragma unroll
    for (int o = 16; o; o >>= 1) accS += __shfl_down_sync(F8, accS, o);
    if (lane == 0) wsum[warp] = accS;
    __syncthreads();
    if (tid == 0) {
        float s = 0.f;
        #pragma unroll
        for (int i = 0; i < 8; i++) s += wsum[i];
        atomicAdd(&g_acc, (double)s);
    }
}

// Writes the scalar result AND resets accumulators for the next graph replay.
__global__ void finalize_kernel(float* out) {
    int t = threadIdx.x;
    if (t == 0) {
        out[0] = (float)(1.0 - g_acc / ((double)BATCH * CH * OW * OW));
        g_acc = 0.0;
    }
    if (t < BATCH) { g_minBits[t] = F8; g_maxBits[t] = 0u; }
}

extern "C" void kernel_launch(void* const* d_in, const int* in_sizes, int n_in,
                              void* d_out, int out_size) {
    const float* img1 = (const float*)d_in[0];
    const float* img2 = (const float*)d_in[1];

    const int smem_bytes = 5 * ITY * 33 * (int)sizeof(float);  // 88,440 B
    cudaFuncSetAttribute(ssim_kernel, cudaFuncAttributeMaxDynamicSharedMemorySize,
                         smem_bytes);

    minmax_kernel<<<dim3(BATCH, 32), 256>>>(img2);
    dim3 grid((OW + TX - 1) / TX, (OW + TY - 1) / TY, BATCH * CH);
    ssim_kernel<<<grid, 256, smem_bytes>>>(img1, img2);
    finalize_kernel<<<1, 64>>>((float*)d_out);
}